// round 2
// baseline (speedup 1.0000x reference)
#include <cuda_runtime.h>
#include <cstdint>
#include <cstddef>

#define B_    2048
#define T_    200
#define D_    64
#define H1_   80
#define H2_   40
#define NROWS (B_*T_)        // 409600
#define NBLK1 (NROWS/128)    // 3200
#define PADV  (-4294967296.0f)

// ---------------- device scratch (no allocations allowed) ----------------
__device__ float g_h1[(size_t)NROWS*H1_];     // 131 MB
__device__ float g_h2[(size_t)NROWS*H2_];     // 65.5 MB
__device__ float g_Wc[128*H1_];               // combined [k | q*k] weights
__device__ float g_qb[B_*H1_];                // per-batch q-projection + b1
__device__ float g_part1[NBLK1*2*H1_];
__device__ float g_part2[NBLK1*2*H2_];
__device__ float g_m1[H1_], g_r1[H1_];
__device__ float g_m2[H2_], g_r2[H2_];
__device__ int   g_mask_mode;                 // 0=u8, 1=i32, 2=f32

// ---------------- f32x2 helpers (sm_103a packed fp32) ----------------
__device__ __forceinline__ unsigned long long dup2(float v) {
    unsigned long long r;
    asm("mov.b64 %0, {%1, %1};" : "=l"(r) : "f"(v));
    return r;
}
__device__ __forceinline__ void fma2(unsigned long long& acc,
                                     unsigned long long a,
                                     unsigned long long b) {
    asm("fma.rn.f32x2 %0, %1, %2, %0;" : "+l"(acc) : "l"(a), "l"(b));
}

// ---------------- mask dtype detection ----------------
// Inspect first 1024 words (4096 bytes) — safe for u8 (409600B), i32, f32.
// i32 bool data: words in {0,1}. f32 bool data: words in {0, 0x3F800000}.
// u8 bool data read as words: values like 0x01010101 -> neither.
__global__ void detect_mask(const unsigned char* __restrict__ m) {
    __shared__ int s_f32ok, s_i32ok, s_f32one, s_i32one;
    if (threadIdx.x == 0) { s_f32ok = 1; s_i32ok = 1; s_f32one = 0; s_i32one = 0; }
    __syncthreads();
    const unsigned* w = (const unsigned*)m;
    int f32ok = 1, i32ok = 1, f32one = 0, i32one = 0;
    for (int i = threadIdx.x; i < 1024; i += 256) {
        unsigned v = w[i];
        if (v != 0u && v != 0x3F800000u) f32ok = 0;
        if (v == 0x3F800000u) f32one = 1;
        if (v != 0u && v != 1u) i32ok = 0;
        if (v == 1u) i32one = 1;
    }
    if (!f32ok) atomicAnd(&s_f32ok, 0);
    if (f32one) atomicOr(&s_f32one, 1);
    if (!i32ok) atomicAnd(&s_i32ok, 0);
    if (i32one) atomicOr(&s_i32one, 1);
    __syncthreads();
    if (threadIdx.x == 0) {
        int mode = 0;
        if (s_f32ok && s_f32one)      mode = 2;
        else if (s_i32ok && s_i32one) mode = 1;
        g_mask_mode = mode;
    }
}

// ---------------- prep: combined weights ----------------
// x@W1 = q@(Wa+Wc) + k@(Wb-Wc) + (q*k)@Wd
__global__ void prep_wc(const float* __restrict__ W1) {
    int i = blockIdx.x * blockDim.x + threadIdx.x;
    if (i >= 128 * H1_) return;
    int d = i / H1_, h = i - d * H1_;
    float v;
    if (d < 64) v = W1[(64 + d) * H1_ + h] - W1[(128 + d) * H1_ + h];
    else        v = W1[(128 + d) * H1_ + h];
    g_Wc[i] = v;
}

// qb[b,h] = b1[h] + sum_d q[b,d] * (W1[d,h] + W1[128+d,h])
__global__ void prep_qb(const float* __restrict__ queries,
                        const float* __restrict__ W1,
                        const float* __restrict__ b1) {
    __shared__ float qs[64];
    int b = blockIdx.x, tid = threadIdx.x;
    if (tid < 64) qs[tid] = queries[b * 64 + tid];
    __syncthreads();
    if (tid < H1_) {
        float acc = b1[tid];
        #pragma unroll 8
        for (int d = 0; d < 64; ++d)
            acc += qs[d] * (W1[d * H1_ + tid] + W1[(128 + d) * H1_ + tid]);
        g_qb[b * H1_ + tid] = acc;
    }
}

// ---------------- K1: h1 = A @ Wc + qb, per-feature sum/sumsq partials ----------------
__global__ void __launch_bounds__(256, 2)
k1(const float* __restrict__ keys, const float* __restrict__ queries) {
    extern __shared__ float sm[];
    float* As = sm;                 // [128][130]
    float* Ws = sm + 128 * 130;     // [128][80]
    int tid = threadIdx.x;
    int row0 = blockIdx.x * 128;

    for (int i = tid; i < 128 * H1_; i += 256) Ws[i] = g_Wc[i];
    for (int i = tid; i < 128 * 128; i += 256) {
        int r = i >> 7, d = i & 127;
        int row = row0 + r;
        float v;
        if (d < 64) {
            v = keys[(size_t)row * 64 + d];
        } else {
            int dd = d - 64;
            v = keys[(size_t)row * 64 + dd] * queries[(row / T_) * 64 + dd];
        }
        As[r * 130 + d] = v;
    }
    __syncthreads();

    int tx = tid & 7, ty = tid >> 3;
    int col0 = tx * 10;
    unsigned long long acc[4][5];
    #pragma unroll
    for (int r = 0; r < 4; ++r)
        #pragma unroll
        for (int j = 0; j < 5; ++j) acc[r][j] = 0ull;

    #pragma unroll 4
    for (int d = 0; d < 128; ++d) {
        const unsigned long long* wp =
            (const unsigned long long*)(Ws + d * H1_ + col0);
        unsigned long long w0 = wp[0], w1 = wp[1], w2 = wp[2], w3 = wp[3], w4 = wp[4];
        #pragma unroll
        for (int r = 0; r < 4; ++r) {
            unsigned long long av = dup2(As[(ty * 4 + r) * 130 + d]);
            fma2(acc[r][0], av, w0);
            fma2(acc[r][1], av, w1);
            fma2(acc[r][2], av, w2);
            fma2(acc[r][3], av, w3);
            fma2(acc[r][4], av, w4);
        }
    }

    float s[10], ss[10];
    #pragma unroll
    for (int j = 0; j < 10; ++j) { s[j] = 0.f; ss[j] = 0.f; }

    #pragma unroll
    for (int r = 0; r < 4; ++r) {
        int row = row0 + ty * 4 + r;
        const float2* qbp = (const float2*)(g_qb + (row / T_) * H1_ + col0);
        float2* op = (float2*)(g_h1 + (size_t)row * H1_ + col0);
        #pragma unroll
        for (int j = 0; j < 5; ++j) {
            float2 qv = qbp[j];
            float lo = __uint_as_float((unsigned)acc[r][j]) + qv.x;
            float hi = __uint_as_float((unsigned)(acc[r][j] >> 32)) + qv.y;
            float2 o; o.x = lo; o.y = hi;
            op[j] = o;
            s[2*j]     += lo; ss[2*j]     += lo * lo;
            s[2*j + 1] += hi; ss[2*j + 1] += hi * hi;
        }
    }

    __syncthreads();
    float* reds  = sm;               // [32][80]
    float* redss = sm + 32 * H1_;    // [32][80]
    #pragma unroll
    for (int j = 0; j < 10; ++j) {
        reds[ty * H1_ + col0 + j]  = s[j];
        redss[ty * H1_ + col0 + j] = ss[j];
    }
    __syncthreads();
    if (tid < H1_) {
        float S = 0.f, SS = 0.f;
        #pragma unroll 8
        for (int i = 0; i < 32; ++i) {
            S  += reds[i * H1_ + tid];
            SS += redss[i * H1_ + tid];
        }
        g_part1[blockIdx.x * (2 * H1_) + tid]       = S;
        g_part1[blockIdx.x * (2 * H1_) + H1_ + tid] = SS;
    }
}

// ---------------- stats: deterministic tree over block partials ----------------
__global__ void stats1() {
    __shared__ float rs[256], rss[256];
    int h = blockIdx.x, tid = threadIdx.x;
    float S = 0.f, SS = 0.f;
    for (int k = tid; k < NBLK1; k += 256) {
        S  += g_part1[k * (2 * H1_) + h];
        SS += g_part1[k * (2 * H1_) + H1_ + h];
    }
    rs[tid] = S; rss[tid] = SS;
    __syncthreads();
    for (int st = 128; st > 0; st >>= 1) {
        if (tid < st) { rs[tid] += rs[tid + st]; rss[tid] += rss[tid + st]; }
        __syncthreads();
    }
    if (tid == 0) {
        float mean = rs[0] / (float)NROWS;
        float var  = rss[0] / (float)NROWS - mean * mean;
        g_m1[h] = mean;
        g_r1[h] = rsqrtf(fmaxf(var, 0.f) + 1e-8f);
    }
}

__global__ void stats2() {
    __shared__ float rs[256], rss[256];
    int h = blockIdx.x, tid = threadIdx.x;
    float S = 0.f, SS = 0.f;
    for (int k = tid; k < NBLK1; k += 256) {
        S  += g_part2[k * (2 * H2_) + h];
        SS += g_part2[k * (2 * H2_) + H2_ + h];
    }
    rs[tid] = S; rss[tid] = SS;
    __syncthreads();
    for (int st = 128; st > 0; st >>= 1) {
        if (tid < st) { rs[tid] += rs[tid + st]; rss[tid] += rss[tid + st]; }
        __syncthreads();
    }
    if (tid == 0) {
        float mean = rs[0] / (float)NROWS;
        float var  = rss[0] / (float)NROWS - mean * mean;
        g_m2[h] = mean;
        g_r2[h] = rsqrtf(fmaxf(var, 0.f) + 1e-8f);
    }
}

// ---------------- K2: h2 = dice(h1) @ W2 + b2, stats partials ----------------
__global__ void __launch_bounds__(256, 4)
k2(const float* __restrict__ W2, const float* __restrict__ b2,
   const float* __restrict__ a1) {
    extern __shared__ float sm[];
    float* A2  = sm;                 // [128][82]
    float* W2s = sm + 128 * 82;      // [80][40]
    __shared__ float pm[H1_], pr[H1_], pa[H1_];
    int tid = threadIdx.x;
    int row0 = blockIdx.x * 128;

    if (tid < H1_) { pm[tid] = g_m1[tid]; pr[tid] = g_r1[tid]; pa[tid] = a1[tid]; }
    for (int i = tid; i < H1_ * H2_; i += 256) W2s[i] = W2[i];
    __syncthreads();

    for (int i = tid; i < 128 * H1_; i += 256) {
        int r = i / H1_, c = i - r * H1_;
        float x  = g_h1[(size_t)row0 * H1_ + i];
        float xn = (x - pm[c]) * pr[c];
        float p  = 1.f / (1.f + __expf(-xn));
        float al = pa[c];
        A2[r * 82 + c] = x * (al + p * (1.f - al));
    }
    __syncthreads();

    int tx = tid & 3, ty = tid >> 2;
    int col0 = tx * 10;
    unsigned long long acc[2][5];
    #pragma unroll
    for (int r = 0; r < 2; ++r)
        #pragma unroll
        for (int j = 0; j < 5; ++j) acc[r][j] = 0ull;

    #pragma unroll 4
    for (int d = 0; d < H1_; ++d) {
        const unsigned long long* wp =
            (const unsigned long long*)(W2s + d * H2_ + col0);
        unsigned long long w0 = wp[0], w1 = wp[1], w2 = wp[2], w3 = wp[3], w4 = wp[4];
        #pragma unroll
        for (int r = 0; r < 2; ++r) {
            unsigned long long av = dup2(A2[(ty * 2 + r) * 82 + d]);
            fma2(acc[r][0], av, w0);
            fma2(acc[r][1], av, w1);
            fma2(acc[r][2], av, w2);
            fma2(acc[r][3], av, w3);
            fma2(acc[r][4], av, w4);
        }
    }

    float s[10], ss[10];
    #pragma unroll
    for (int j = 0; j < 10; ++j) { s[j] = 0.f; ss[j] = 0.f; }

    #pragma unroll
    for (int r = 0; r < 2; ++r) {
        int row = row0 + ty * 2 + r;
        const float2* bp = (const float2*)(b2 + col0);
        float2* op = (float2*)(g_h2 + (size_t)row * H2_ + col0);
        #pragma unroll
        for (int j = 0; j < 5; ++j) {
            float2 bv = bp[j];
            float lo = __uint_as_float((unsigned)acc[r][j]) + bv.x;
            float hi = __uint_as_float((unsigned)(acc[r][j] >> 32)) + bv.y;
            float2 o; o.x = lo; o.y = hi;
            op[j] = o;
            s[2*j]     += lo; ss[2*j]     += lo * lo;
            s[2*j + 1] += hi; ss[2*j + 1] += hi * hi;
        }
    }

    __syncthreads();
    float* reds  = sm;               // [64][40]
    float* redss = sm + 64 * H2_;    // [64][40]
    #pragma unroll
    for (int j = 0; j < 10; ++j) {
        reds[ty * H2_ + col0 + j]  = s[j];
        redss[ty * H2_ + col0 + j] = ss[j];
    }
    __syncthreads();
    if (tid < H2_) {
        float S = 0.f, SS = 0.f;
        #pragma unroll 8
        for (int i = 0; i < 64; ++i) {
            S  += reds[i * H2_ + tid];
            SS += redss[i * H2_ + tid];
        }
        g_part2[blockIdx.x * (2 * H2_) + tid]       = S;
        g_part2[blockIdx.x * (2 * H2_) + H2_ + tid] = SS;
    }
}

// ---------------- K3: scores + mask + softmax + weighted key sum ----------------
__global__ void __launch_bounds__(256)
k3(const float* __restrict__ keys, const unsigned char* __restrict__ maskraw,
   const float* __restrict__ W3, const float* __restrict__ b3,
   const float* __restrict__ a2p, float* __restrict__ out) {
    __shared__ float sw[H2_], sm2[H2_], sr2[H2_], sa2[H2_];
    __shared__ float sc[T_];
    __shared__ float red[256];
    __shared__ float osum[256];
    int b = blockIdx.x, tid = threadIdx.x;
    int mode = g_mask_mode;

    if (tid < H2_) {
        sw[tid]  = W3[tid];
        sm2[tid] = g_m2[tid];
        sr2[tid] = g_r2[tid];
        sa2[tid] = a2p[tid];
    }
    __syncthreads();

    if (tid < T_) {
        const float* hp = g_h2 + (size_t)(b * T_ + tid) * H2_;
        float acc = b3[0];
        #pragma unroll
        for (int h = 0; h < H2_; ++h) {
            float x  = hp[h];
            float xn = (x - sm2[h]) * sr2[h];
            float p  = 1.f / (1.f + __expf(-xn));
            float al = sa2[h];
            acc += x * (al + p * (1.f - al)) * sw[h];
        }
        int idx = b * T_ + tid;
        bool mv;
        if (mode == 2)      mv = (((const float*)maskraw)[idx] != 0.0f);
        else if (mode == 1) mv = (((const int*)maskraw)[idx] != 0);
        else                mv = (maskraw[idx] != 0);
        sc[tid] = mv ? acc : PADV;
    }
    __syncthreads();

    red[tid] = (tid < T_) ? sc[tid] : -3.4e38f;
    __syncthreads();
    for (int st = 128; st > 0; st >>= 1) {
        if (tid < st) red[tid] = fmaxf(red[tid], red[tid + st]);
        __syncthreads();
    }
    float m = red[0];
    __syncthreads();

    float e = 0.f;
    if (tid < T_) e = __expf(sc[tid] - m);
    red[tid] = e;
    __syncthreads();
    for (int st = 128; st > 0; st >>= 1) {
        if (tid < st) red[tid] += red[tid + st];
        __syncthreads();
    }
    float inv = 1.0f / red[0];
    if (tid < T_) sc[tid] = e * inv;
    __syncthreads();

    int d = tid & 63, seg = tid >> 6;
    float acc2 = 0.f;
    const float* kp = keys + ((size_t)b * T_ + seg * 50) * 64 + d;
    #pragma unroll 5
    for (int t = 0; t < 50; ++t) acc2 += sc[seg * 50 + t] * kp[(size_t)t * 64];
    osum[tid] = acc2;
    __syncthreads();
    if (tid < 64)
        out[b * 64 + tid] =
            (osum[tid] + osum[64 + tid]) + (osum[128 + tid] + osum[192 + tid]);
}

// ---------------- launch ----------------
extern "C" void kernel_launch(void* const* d_in, const int* in_sizes, int n_in,
                              void* d_out, int out_size) {
    const float* queries = (const float*)d_in[0];
    const float* keys    = (const float*)d_in[1];
    const unsigned char* mask = (const unsigned char*)d_in[2];
    const float* W1 = (const float*)d_in[3];
    const float* b1 = (const float*)d_in[4];
    const float* a1 = (const float*)d_in[5];
    const float* W2 = (const float*)d_in[6];
    const float* b2 = (const float*)d_in[7];
    const float* a2 = (const float*)d_in[8];
    const float* W3 = (const float*)d_in[9];
    const float* b3 = (const float*)d_in[10];
    float* out = (float*)d_out;

    int smem1 = (128 * 130 + 128 * H1_) * 4;   // 107,520 B
    int smem2 = (128 * 82 + H1_ * H2_) * 4;    //  54,784 B
    cudaFuncSetAttribute(k1, cudaFuncAttributeMaxDynamicSharedMemorySize, smem1);
    cudaFuncSetAttribute(k2, cudaFuncAttributeMaxDynamicSharedMemorySize, smem2);

    detect_mask<<<1, 256>>>(mask);
    prep_wc<<<(128 * H1_ + 255) / 256, 256>>>(W1);
    prep_qb<<<B_, 128>>>(queries, W1, b1);
    k1<<<NBLK1, 256, smem1>>>(keys, queries);
    stats1<<<H1_, 256>>>();
    k2<<<NBLK1, 256, smem2>>>(W2, b2, a1);
    stats2<<<H2_, 256>>>();
    k3<<<B_, 256>>>(keys, mask, W3, b3, a2, out);
}